// round 14
// baseline (speedup 1.0000x reference)
#include <cuda_runtime.h>
#include <math.h>

#define PI 3.14159265358979323846

#define BATCH 8
#define NPTS  1024
#define F0    100
#define F1    100
#define NCLS  40

#define NA60  60
#define L1MAX 16
#define N32   32
#define L2MAX 10
#define N20   20

#define NC1   256
#define NH1   2856   // sum_{l<16} (l+1)(2l+1)
#define NH2   715    // sum_{l<10} (l+1)(2l+1)
#define NSQ2  1330   // sum_{l<10} (2l+1)^2
#define MR1   31
#define MR2   19

__device__ __forceinline__ int offsq(int l){ return l*(4*l*l-1)/3; }
__device__ __forceinline__ int hoff(int l){
    return ((l-1)*l*(2*l-1))/3 + (3*(l-1)*l)/2 + l;
}
__device__ __forceinline__ void unpack_h(int p, int &l, int &m, int &jn){
    l=0; while (p >= (l+1)*(2*l+1)){ p -= (l+1)*(2*l+1); l++; }
    m = p/(2*l+1); jn = p%(2*l+1);
}

// ---------------- scratch ----------------
__device__ float2 g_X1 [BATCH*NC1];
__device__ float2 g_Y1 [F0*NC1];
__device__ float  g_h1 [BATCH*F0*N32*N32*N32];
__device__ float  g_bn1a[F0], g_bn1bv[F0];
__device__ float2 g_Wh2[F0*F1*MR2];
__device__ float2 g_Aah[BATCH*F0*NH2];
__device__ float2 g_Z2h[BATCH*F1*NH2];
__device__ float  g_h2 [BATCH*F1*N20*N20*N20];
__device__ float  g_bn2a[F1], g_bn2bv[F1];
__device__ float  g_feat[BATCH*F1];
__device__ double2 g_s1p[BATCH*F0];
__device__ double2 g_s2p[BATCH*F1];

// ---------------- tables ----------------
__device__ float g_d16h  [N32*NH1];
__device__ float g_d10h  [N20*NH2];
__device__ float g_dh10  [NSQ2];
__device__ float g_dcol30[NA60*NC1];
__device__ float g_dhcol [NC1];
__device__ float g_qw30[NA60], g_qw16[N32], g_qw10[N20];

// ============ Wigner-d ============
__device__ double d_ipow(double x, int n){ double r=1.0; for(int i=0;i<n;i++) r*=x; return r; }

__device__ double d_wig(int l, int mp, int m, double beta, const double* f){
    if (l == 0) return 1.0;
    double cb = cos(0.5*beta), sb = sin(0.5*beta);
    int smin = max(0, m-mp);
    int smax = min(l+m, l-mp);
    double pref = sqrt(f[l+mp]*f[l-mp]*f[l+m]*f[l-m]);
    double term = d_ipow(cb, 2*l+m-mp-2*smin) * d_ipow(sb, mp-m+2*smin)
                / (f[l+m-smin]*f[smin]*f[mp-m+smin]*f[l-mp-smin]);
    if ((mp-m+smin)&1) term = -term;
    double acc = term;
    double r2 = (sb*sb)/(cb*cb);
    for (int s=smin; s<smax; s++){
        term *= -r2 * (double)((l+m-s)*(l-mp-s)) / ((double)(s+1)*(double)(mp-m+s+1));
        acc += term;
    }
    return pref*acc;
}

#define T0c (N32*NH1)
#define T1c (N20*NH2)
#define T2c (NSQ2)
#define T3c (NA60*NC1)
#define T4c (NC1)
#define T5c (112)
#define TSETUP (T0c+T1c+T2c+T3c+T4c+T5c)

__global__ void k_setup(){
    __shared__ double f[32];
    if (threadIdx.x == 0){ f[0]=1.0; for (int i=1;i<32;i++) f[i]=f[i-1]*(double)i; }
    __syncthreads();
    int tid = blockIdx.x*blockDim.x + threadIdx.x;
    if (tid >= TSETUP) return;
    if (tid < T0c){
        int k = tid/NH1;
        if (k >= 16) return;
        int p = tid%NH1;
        int l,m,jn; unpack_h(p,l,m,jn);
        double beta = PI*(2*k+1)/64.0;
        g_d16h[tid] = (float)d_wig(l, m, jn-l, beta, f);
        return;
    }
    tid -= T0c;
    if (tid < T1c){
        int k = tid/NH2;
        if (k >= 10) return;
        int p = tid%NH2;
        int l,m,jn; unpack_h(p,l,m,jn);
        double beta = PI*(2*k+1)/40.0;
        g_d10h[tid] = (float)d_wig(l, m, jn-l, beta, f);
        return;
    }
    tid -= T1c;
    if (tid < T2c){
        int p = tid;
        int l=0; while (p >= (2*l+1)*(2*l+1)){ p -= (2*l+1)*(2*l+1); l++; }
        int jm = p/(2*l+1), jn = p%(2*l+1);
        g_dh10[tid] = (float)d_wig(l, jm-l, jn-l, 0.5*PI, f);
        return;
    }
    tid -= T2c;
    if (tid < T3c){
        int k = tid/NC1;
        if (k >= 30) return;
        int p = tid%NC1;
        int l=0; while ((l+1)*(l+1) <= p) l++;
        int jm = p - l*l;
        double beta = PI*(2*k+1)/120.0;
        g_dcol30[tid] = (float)d_wig(l, jm-l, 0, beta, f);
        return;
    }
    tid -= T3c;
    if (tid < T4c){
        int p = tid;
        int l=0; while ((l+1)*(l+1) <= p) l++;
        int jm = p - l*l;
        g_dhcol[tid] = (float)d_wig(l, jm-l, 0, 0.5*PI, f);
        return;
    }
    tid -= T4c;
    {
        int bgrid, k; float* out;
        if (tid < 60){ bgrid=30; out=g_qw30; k=tid; }
        else if (tid < 92){ bgrid=16; out=g_qw16; k=tid-60; }
        else { bgrid=10; out=g_qw10; k=tid-92; }
        double beta = PI*(2*k+1)/(4.0*bgrid);
        double s = 0.0;
        for (int j=0;j<bgrid;j++)
            s += sin((double)(2*k+1)*(2*j+1)*PI/(4.0*bgrid))/(double)(2*j+1);
        out[k] = (float)((2.0/bgrid)*sin(beta)*s);
    }
}

// pre: blocks 0..99 = wh1+y1; blocks 100.. = table mirror
#define M0c (16*NH1)
#define M1c (10*NH2)
#define M3c (30*NC1)
#define MTOT (M0c+M1c+M3c)
#define PREGRID (100 + (MTOT+255)/256)

__global__ void k_pre(const float* __restrict__ w_s2){
    int t = threadIdx.x;
    if (blockIdx.x < 100){
        int o = blockIdx.x;
        __shared__ float2 tab[NA60];
        __shared__ float2 wh[MR1];
        if (t < NA60){ double s,c; sincospi(-2.0*t/60.0,&s,&c); tab[t]=make_float2((float)c,(float)s); }
        __syncthreads();
        if (t < MR1){
            int m = t - 15;
            int inc = ((m%60)+60)%60;
            float sr=0.0f, si=0.0f;
            const float* w = w_s2 + o*NA60;
            int idx=0;
            for (int p=0;p<NA60;p++){
                float2 e = tab[idx];
                sr += w[p]*e.x; si += w[p]*e.y;
                idx += inc; if (idx>=60) idx-=60;
            }
            wh[t] = make_float2(sr,si);
        }
        __syncthreads();
        {
            int p = t;
            int l=0; while ((l+1)*(l+1) <= p) l++;
            int m = (p - l*l) - l;
            float d = g_dhcol[p] * (1.0f/60.0f);
            float2 w = wh[m+15];
            g_Y1[o*NC1+p] = make_float2(d*w.x, d*w.y);
        }
        return;
    }
    int idx = (blockIdx.x-100)*256 + t;
    if (idx >= MTOT) return;
    if (idx < M0c){
        int kk = 16 + idx/NH1;
        int p = idx%NH1;
        int l,m,jn; unpack_h(p,l,m,jn);
        float v = g_d16h[(31-kk)*NH1 + p + 2*(l-jn)];
        g_d16h[kk*NH1 + p] = ((l+m)&1) ? -v : v;
        return;
    }
    idx -= M0c;
    if (idx < M1c){
        int kk = 10 + idx/NH2;
        int p = idx%NH2;
        int l,m,jn; unpack_h(p,l,m,jn);
        float v = g_d10h[(19-kk)*NH2 + p + 2*(l-jn)];
        g_d10h[kk*NH2 + p] = ((l+m)&1) ? -v : v;
        return;
    }
    idx -= M1c;
    {
        int kk = 30 + idx/NC1;
        int p = idx%NC1;
        int l=0; while ((l+1)*(l+1) <= p) l++;
        int jm = p - l*l;
        float v = g_dcol30[(59-kk)*NC1 + p];
        g_dcol30[kk*NC1 + p] = (jm&1) ? -v : v;
    }
}

// front: one block per batch
__global__ void k_front(const float* __restrict__ x){
    __shared__ float  img[NA60*NA60];
    __shared__ float2 Gas[NA60*MR1];
    __shared__ float2 tab[NA60];
    int b = blockIdx.x;
    int t = threadIdx.x;
    for (int i=t; i<NA60*NA60; i+=256) img[i]=0.0f;
    if (t < NA60){ double s,c; sincospi(-2.0*t/60.0,&s,&c); tab[t]=make_float2((float)c,(float)s); }
    __syncthreads();
    for (int p=t; p<NPTS; p+=256){
        float xx = x[b*3*NPTS + 0*NPTS + p];
        float yy = x[b*3*NPTS + 1*NPTS + p];
        float zz = x[b*3*NPTS + 2*NPTS + p];
        float r  = sqrtf(xx*xx + yy*yy + zz*zz);
        float rc = fmaxf(r, 1e-8f);
        float cz = fminf(fmaxf(zz/rc, -1.0f), 1.0f);
        float beta  = acosf(cz);
        float alpha = atan2f(yy, xx);
        if (alpha < 0.0f) alpha += 2.0f*(float)PI;
        int bi = (int)(beta/(float)PI*60.0f);          bi = min(max(bi,0),59);
        int ai = (int)(alpha/(2.0f*(float)PI)*60.0f);  ai = min(max(ai,0),59);
        atomicMax((int*)&img[bi*NA60+ai], __float_as_int(r));
    }
    __syncthreads();
    for (int e=t; e<NA60*MR1; e+=256){
        int j = e % MR1, k = e / MR1;
        int m = j - 15;
        int inc = ((m%60)+60)%60;
        float sr=0.0f, si=0.0f;
        const float* row = img + k*NA60;
        int idx=0;
        #pragma unroll 4
        for (int a=0;a<NA60;a++){
            float2 w = tab[idx];
            float v = row[a];
            sr += v*w.x; si += v*w.y;
            idx += inc; if (idx>=60) idx-=60;
        }
        Gas[e] = make_float2(sr,si);
    }
    __syncthreads();
    {
        int p = t;
        int l=0; while ((l+1)*(l+1) <= p) l++;
        int m = (p - l*l) - l;
        float ar=0.0f, ai=0.0f;
        for (int k=0;k<NA60;k++){
            float wd = g_qw30[k]*g_dcol30[k*NC1 + p];
            float2 ga = Gas[k*MR1 + (m+15)];
            ar += wd*ga.x; ai += wd*ga.y;
        }
        float sc = (float)(2.0*PI/60.0);
        g_X1[b*NC1+p] = make_float2(ar*sc, ai*sc);
    }
}

// layer-1 synthesis: merged M-build+fold into float4 PQ, twiddle pairs, Parseval.
// Block per (b,o).
__global__ void k_syn1(){
    __shared__ float2 Zv [NH1];
    __shared__ float2 M0sh[16];
    __shared__ float4 PQ4[16*15];      // (Pr,Pi,Qr,Qi) for n=1..15
    __shared__ float2 Tsh[16*N32];
    __shared__ float2 Xsh[NC1], Ysh[NC1];
    __shared__ float2 ctab[N32];
    __shared__ double red[256], red2[256];
    int bo = blockIdx.x;
    int o = bo % F0, b = bo / F0;
    int t = threadIdx.x;
    for (int i=t;i<NC1;i+=256){ Xsh[i]=g_X1[b*NC1+i]; Ysh[i]=g_Y1[o*NC1+i]; }
    if (t < N32){ double s,c; sincospi(2.0*t/32.0,&s,&c); ctab[t]=make_float2((float)c,(float)s); }
    __syncthreads();
    for (int ph=t; ph<NH1; ph+=256){
        int l,m,jn; unpack_h(ph,l,m,jn);
        float2 xv = Xsh[l*l + m+l];
        float2 yv = Ysh[l*l + jn];
        float w = (float)(2*l+1);
        Zv[ph] = make_float2(w*(xv.x*yv.x + xv.y*yv.y),
                             w*(xv.y*yv.x - xv.x*yv.y));
    }
    double hs=0.0, dsq=0.0;
    float* hbase = g_h1 + (size_t)bo * 32768;
    const int m_ = t >> 4, n_ = t & 15;
    const int lmin_ = max(m_, n_);
    const int idx0_ = hoff(lmin_) + m_*(2*lmin_+1) + (n_+lmin_);
    const int d0_ = (lmin_+1)*(2*lmin_+1) + 2*m_ + 1;
    const int u0_ = 4*lmin_ + 5;
    const int n2_ = 2*n_;
    for (int k=0;k<N32;k++){
        __syncthreads();
        const float* dk = g_d16h + k*NH1;
        // ---- merged M-build + PQ-fold ----
        {
            int idx = idx0_, delta = d0_, upd = u0_;
            float arp=0.0f, aip=0.0f, arm=0.0f, aim=0.0f;
            for (int l=lmin_; l<L1MAX; l++){
                float wp = dk[idx];
                float2 zp = Zv[idx];
                arp = fmaf(wp, zp.x, arp); aip = fmaf(wp, zp.y, aip);
                int idm = idx - n2_;
                float wm = dk[idm];
                float2 zm = Zv[idm];
                arm = fmaf(wm, zm.x, arm); aim = fmaf(wm, zm.y, aim);
                idx += delta; delta += upd; upd += 4;
            }
            float w2 = (m_>0) ? 2.0f : 1.0f;
            if (n_ == 0){
                M0sh[m_] = make_float2(arp, aip);
                dsq += (double)(w2*(arp*arp + aip*aip));
                if (t == 0) hs += (double)arp;
            } else {
                PQ4[m_*15 + n_-1] = make_float4(arp+arm, aip+aim, arp-arm, aip-aim);
                dsq += (double)(w2*(arp*arp + aip*aip + arm*arm + aim*aim));
            }
        }
        __syncthreads();
        // ---- T-stage: float4 PQ loads ----
        for (int e=t; e<272; e+=256){
            int m = e/17, g = e%17;
            float2 M0 = M0sh[m];
            float tr1=M0.x, ti1=M0.y, tr2=M0.x, ti2=M0.y;
            int idx = g, step = g;
            #pragma unroll
            for (int n=1;n<16;n++){
                float2 w = ctab[idx];
                float4 q = PQ4[m*15 + n-1];      // (Pr,Pi,Qr,Qi)
                float pcx = q.x*w.x, pcy = q.y*w.x;
                float qsx = q.z*w.y, qsy = q.w*w.y;
                tr1 += pcx - qsy; ti1 += pcy + qsx;
                tr2 += pcx + qsy; ti2 += pcy - qsx;
                idx = (idx+step)&31;
            }
            float sc = (m>0) ? 2.0f : 1.0f;
            Tsh[m*N32+g] = make_float2(sc*tr1, sc*ti1);
            if (g!=0 && g!=16) Tsh[m*N32+32-g] = make_float2(sc*tr2, sc*ti2);
        }
        __syncthreads();
        // ---- H-stage ----
        float* hout = hbase + k*1024;
        for (int e=t; e<544; e+=256){
            int a = e >> 5, g = e & 31;
            float acc1 = Tsh[g].x, acc2 = acc1;
            int idx = a, step = a;
            #pragma unroll
            for (int m=1;m<16;m++){
                float2 w = ctab[idx];
                float2 tv = Tsh[m*N32+g];
                float p1 = tv.x*w.x, p2 = tv.y*w.y;
                acc1 += p1 - p2;
                acc2 += p1 + p2;
                idx = (idx+step)&31;
            }
            hout[a*32+g] = acc1;
            if (a!=0 && a!=16) hout[(32-a)*32+g] = acc2;
        }
    }
    red[t]=hs; red2[t]=dsq; __syncthreads();
    for (int st=128; st>0; st>>=1){ if (t<st){ red[t]+=red[t+st]; red2[t]+=red2[t+st]; } __syncthreads(); }
    if (t==0) g_s1p[bo] = make_double2(1024.0*red[0], 1024.0*red2[0]);
}

// bnw: blocks 0..99 = bn1fin; blocks 100.. = wh2
__global__ void k_bnw(const float* __restrict__ gw, const float* __restrict__ gb,
                      const float* __restrict__ w_so3){
    int t = threadIdx.x;
    if (blockIdx.x < 100){
        int o = blockIdx.x;
        if (t >= 32) return;
        double s=0.0, s2=0.0;
        if (t < BATCH){ double2 p = g_s1p[t*F0+o]; s=p.x; s2=p.y; }
        for (int st=4; st>0; st>>=1){
            s  += __shfl_down_sync(0xffffffffu, s,  st);
            s2 += __shfl_down_sync(0xffffffffu, s2, st);
        }
        if (t==0){
            double N = (double)BATCH*32768.0;
            double mu = s/N;
            double var = s2/N - mu*mu;
            float a = gw[o] * (float)rsqrt(var + 1e-5);
            g_bn1a[o]=a; g_bn1bv[o]= gb[o] - (float)mu * a;
        }
        return;
    }
    __shared__ float2 tab[N32];
    if (t<N32){ double s,c; sincospi(-2.0*t/32.0,&s,&c); tab[t]=make_float2((float)c,(float)s); }
    __syncthreads();
    int tid = (blockIdx.x-100)*256 + t;
    if (tid >= F0*F1*MR2) return;
    int j = tid % MR2; int io = tid / MR2;
    int m = j - 9;
    int inc = m & 31;
    float sr=0.0f, si=0.0f;
    const float* w = w_so3 + io*N32;
    int idx=0;
    #pragma unroll
    for (int p=0;p<N32;p++){
        float2 e = tab[idx];
        sr += w[p]*e.x; si += w[p]*e.y;
        idx=(idx+inc)&31;
    }
    g_Wh2[tid] = make_float2(sr*(1.0f/32.0f), si*(1.0f/32.0f));
}

// fused BN+relu + half fft2 + beta-quadrature + pi/2 contraction. Block per (b,c).
__global__ void k_g2f(){
    __shared__ float  hsh[N32*N32];
    __shared__ float  Sph[15*N32], Smh[15*N32];
    __shared__ float2 Ush[10*N32];
    __shared__ float2 Gsh[10*MR2];
    __shared__ float2 ctab[N32];
    __shared__ float2 X2sh[NH2];
    int bc = blockIdx.x;
    int c = bc % F0;
    int t = threadIdx.x;
    float a1 = g_bn1a[c], b1 = g_bn1bv[c];
    if (t<N32){ double s,cc; sincospi(2.0*t/32.0,&s,&cc); ctab[t]=make_float2((float)cc,(float)s); }
    int pm[3], pcol[3];
    float axr[3]={0,0,0}, axi[3]={0,0,0};
    {
        int i=0;
        for (int p=t; p<NH2; p+=256){
            int l,m,jn; unpack_h(p,l,m,jn);
            pm[i]=m; pcol[i]=jn-l+9; i++;
        }
    }
    const float* hbase = g_h1 + (size_t)bc*32768;
    for (int k=0;k<N32;k++){
        __syncthreads();
        const float* hin = hbase + k*1024;
        for (int i=t;i<1024;i+=256){ float v = hin[i]*a1 + b1; hsh[i] = v>0.0f ? v : 0.0f; }
        __syncthreads();
        for (int e=t; e<480; e+=256){
            int a = e/32 + 1, g = e%32;
            float u = hsh[a*32+g], v = hsh[(32-a)*32+g];
            Sph[(a-1)*32+g] = u+v;
            Smh[(a-1)*32+g] = u-v;
        }
        __syncthreads();
        for (int e=t; e<320; e+=256){
            int m = e/32, g = e%32;
            float h16 = hsh[16*32+g];
            float ur = hsh[g] + ((m&1) ? -h16 : h16);
            float ui = 0.0f;
            int idx = m&31, step = m;
            #pragma unroll
            for (int a=1;a<16;a++){
                float2 w = ctab[idx];
                ur += Sph[(a-1)*32+g]*w.x;
                ui -= Smh[(a-1)*32+g]*w.y;
                idx = (idx+step)&31;
            }
            Ush[m*32+g] = make_float2(ur,ui);
        }
        __syncthreads();
        for (int e=t; e<100; e+=256){
            int m = e/10, n = e%10;
            float g1r=0,g1i=0,g2r=0,g2i=0;
            int idx=0;
            #pragma unroll 4
            for (int g=0; g<N32; g++){
                float2 w = ctab[idx];
                float2 u = Ush[m*32+g];
                float xc=u.x*w.x, ys=u.y*w.y, yc=u.y*w.x, xs=u.x*w.y;
                g1r += xc+ys; g1i += yc-xs;
                g2r += xc-ys; g2i += yc+xs;
                idx = (idx+n)&31;
            }
            Gsh[m*MR2 + 9+n] = make_float2(g1r,g1i);
            if (n) Gsh[m*MR2 + 9-n] = make_float2(g2r,g2i);
        }
        __syncthreads();
        {
            float qk = g_qw16[k];
            const float* dk = g_d16h + k*NH1;
            int i=0;
            for (int p=t; p<NH2; p+=256){
                float wd = qk*dk[p];
                float2 gg = Gsh[pm[i]*MR2 + pcol[i]];
                axr[i] += wd*gg.x; axi[i] += wd*gg.y; i++;
            }
        }
    }
    __syncthreads();
    {
        float sc = (float)((2.0*PI/32.0)*(2.0*PI/32.0));
        int i=0;
        for (int p=t; p<NH2; p+=256){ X2sh[p]=make_float2(axr[i]*sc, axi[i]*sc); i++; }
    }
    __syncthreads();
    float2* Aout = g_Aah + (size_t)bc*NH2;
    for (int p=t; p<NH2; p+=256){
        int l,m,jn; unpack_h(p,l,m,jn);
        int w = 2*l+1;
        const float2* X = X2sh + hoff(l) + m*w;
        const float*  dd = g_dh10 + offsq(l) + jn*w;
        float ar=0.0f, ai=0.0f;
        for (int jk=0; jk<w; jk++){ ar += dd[jk]*X[jk].x; ai += dd[jk]*X[jk].y; }
        Aout[p] = make_float2(ar,ai);
    }
}

// Z2 half with 4-way o tiling
__global__ void k_z2(){
    int tid = blockIdx.x*blockDim.x + threadIdx.x;
    if (tid >= BATCH*25*NH2) return;
    int p = tid % NH2; int rest = tid / NH2;
    int oq = rest % 25; int b = rest / 25;
    int l,m,jn; unpack_h(p,l,m,jn);
    int jw = (jn - l) + 9;
    float ar0=0,ai0=0,ar1=0,ai1=0,ar2=0,ai2=0,ar3=0,ai3=0;
    const float2* A = g_Aah + (size_t)b*F0*NH2 + p;
    const float2* W = g_Wh2 + oq*MR2 + jw;
    #pragma unroll 2
    for (int i=0;i<F0;i++){
        float2 a = A[(size_t)i*NH2];
        const float2* Wi = W + (size_t)i*F1*MR2;
        float2 w0 = Wi[0*25*MR2];
        float2 w1 = Wi[1*25*MR2];
        float2 w2 = Wi[2*25*MR2];
        float2 w3 = Wi[3*25*MR2];
        ar0 += a.x*w0.x + a.y*w0.y;  ai0 += a.y*w0.x - a.x*w0.y;
        ar1 += a.x*w1.x + a.y*w1.y;  ai1 += a.y*w1.x - a.x*w1.y;
        ar2 += a.x*w2.x + a.y*w2.y;  ai2 += a.y*w2.x - a.x*w2.y;
        ar3 += a.x*w3.x + a.y*w3.y;  ai3 += a.y*w3.x - a.x*w3.y;
    }
    size_t base = (size_t)(b*F1)*NH2 + p;
    g_Z2h[base + (size_t)(oq   )*NH2] = make_float2(ar0,ai0);
    g_Z2h[base + (size_t)(oq+25)*NH2] = make_float2(ar1,ai1);
    g_Z2h[base + (size_t)(oq+50)*NH2] = make_float2(ar2,ai2);
    g_Z2h[base + (size_t)(oq+75)*NH2] = make_float2(ar3,ai3);
}

// layer-2 synthesis: merged M-build+fold (float4 PQ) + Parseval. Block per (b,o).
__global__ void k_syn2(){
    __shared__ float2 Zsh[NH2];
    __shared__ float2 M0sh[10];
    __shared__ float4 PQ4[10*9];
    __shared__ float2 Tsh[10*N20];
    __shared__ float2 ctab[N20];
    __shared__ double red[256], red2[256];
    int bo = blockIdx.x;
    int t = threadIdx.x;
    if (t < N20){ double s,c; sincospi(2.0*t/20.0,&s,&c); ctab[t]=make_float2((float)c,(float)s); }
    for (int ph=t; ph<NH2; ph+=256){
        int l,m,jn; unpack_h(ph,l,m,jn);
        float2 z = g_Z2h[(size_t)bo*NH2 + ph];
        float w = (float)(2*l+1);
        Zsh[ph] = make_float2(w*z.x, w*z.y);
    }
    double hs=0.0, dsq=0.0;
    float* hbase = g_h2 + (size_t)bo*8000;
    int m_=0, n_=0, lmin_=0, idx0_=0, d0_=0, u0_=0, n2_=0;
    if (t < 100){
        m_ = t/10; n_ = t%10;
        lmin_ = max(m_, n_);
        idx0_ = hoff(lmin_) + m_*(2*lmin_+1) + (n_+lmin_);
        d0_ = (lmin_+1)*(2*lmin_+1) + 2*m_ + 1;
        u0_ = 4*lmin_ + 5;
        n2_ = 2*n_;
    }
    for (int k=0;k<N20;k++){
        __syncthreads();
        const float* dk = g_d10h + k*NH2;
        if (t < 100){
            int idx = idx0_, delta = d0_, upd = u0_;
            float arp=0.0f, aip=0.0f, arm=0.0f, aim=0.0f;
            for (int l=lmin_; l<L2MAX; l++){
                float wp = dk[idx];
                float2 zp = Zsh[idx];
                arp = fmaf(wp, zp.x, arp); aip = fmaf(wp, zp.y, aip);
                int idm = idx - n2_;
                float wm = dk[idm];
                float2 zm = Zsh[idm];
                arm = fmaf(wm, zm.x, arm); aim = fmaf(wm, zm.y, aim);
                idx += delta; delta += upd; upd += 4;
            }
            float w2 = (m_>0) ? 2.0f : 1.0f;
            if (n_ == 0){
                M0sh[m_] = make_float2(arp, aip);
                dsq += (double)(w2*(arp*arp + aip*aip));
                if (t == 0) hs += (double)arp;
            } else {
                PQ4[m_*9 + n_-1] = make_float4(arp+arm, aip+aim, arp-arm, aip-aim);
                dsq += (double)(w2*(arp*arp + aip*aip + arm*arm + aim*aim));
            }
        }
        __syncthreads();
        for (int e=t; e<110; e+=256){
            int m = e/11, g = e%11;
            float2 M0 = M0sh[m];
            float tr1=M0.x, ti1=M0.y, tr2=M0.x, ti2=M0.y;
            int idx = g, step = g;
            #pragma unroll
            for (int n=1;n<10;n++){
                float2 w = ctab[idx];
                float4 q = PQ4[m*9 + n-1];
                float pcx = q.x*w.x, pcy = q.y*w.x;
                float qsx = q.z*w.y, qsy = q.w*w.y;
                tr1 += pcx - qsy; ti1 += pcy + qsx;
                tr2 += pcx + qsy; ti2 += pcy - qsx;
                idx += step; if (idx>=20) idx-=20;
            }
            float sc = (m>0) ? 2.0f : 1.0f;
            Tsh[m*N20+g] = make_float2(sc*tr1, sc*ti1);
            if (g!=0 && g!=10) Tsh[m*N20+20-g] = make_float2(sc*tr2, sc*ti2);
        }
        __syncthreads();
        float* hout = hbase + k*400;
        for (int e=t; e<220; e+=256){
            int a = e/20, g = e%20;
            float acc1 = Tsh[g].x, acc2 = acc1;
            int idx = a, step = a;
            #pragma unroll
            for (int m=1;m<10;m++){
                float2 w = ctab[idx];
                float2 tv = Tsh[m*N20+g];
                float p1 = tv.x*w.x, p2 = tv.y*w.y;
                acc1 += p1 - p2;
                acc2 += p1 + p2;
                idx += step; if (idx>=20) idx-=20;
            }
            hout[a*20+g] = acc1;
            if (a!=0 && a!=10) hout[(20-a)*20+g] = acc2;
        }
    }
    red[t]=hs; red2[t]=dsq; __syncthreads();
    for (int st=128; st>0; st>>=1){ if (t<st){ red[t]+=red[t+st]; red2[t]+=red2[t+st]; } __syncthreads(); }
    if (t==0) g_s2p[bo] = make_double2(400.0*red[0], 400.0*red2[0]);
}

__global__ void k_bn2fin(const float* __restrict__ gw, const float* __restrict__ gb){
    int o = blockIdx.x; int t = threadIdx.x;
    double s=0.0, s2=0.0;
    if (t < BATCH){ double2 p = g_s2p[t*F1+o]; s=p.x; s2=p.y; }
    for (int st=4; st>0; st>>=1){
        s  += __shfl_down_sync(0xffffffffu, s,  st);
        s2 += __shfl_down_sync(0xffffffffu, s2, st);
    }
    if (t==0){
        double N = (double)BATCH*8000.0;
        double mu = s/N;
        double var = s2/N - mu*mu;
        float a = gw[o] * (float)rsqrt(var + 1e-5);
        g_bn2a[o]=a; g_bn2bv[o]= gb[o] - (float)mu * a;
    }
}

__global__ void k_integrate(){
    int bf = blockIdx.x;
    int f = bf % F1;
    int t = threadIdx.x;
    float a = g_bn2a[f], bb = g_bn2bv[f];
    double s = 0.0;
    const float* h = g_h2 + (size_t)bf*8000;
    for (int idx=t; idx<8000; idx+=256){
        int k = idx/400;
        float v = h[idx]*a + bb;
        v = v>0.0f ? v : 0.0f;
        s += (double)v * (double)g_qw10[k];
    }
    __shared__ double sh[256];
    sh[t]=s; __syncthreads();
    for (int st=128; st>0; st>>=1){ if (t<st) sh[t]+=sh[t+st]; __syncthreads(); }
    if (t==0){
        double sc = (2.0*PI/20.0)*(2.0*PI/20.0);
        g_feat[bf] = (float)(sh[0]*sc);
    }
}

__global__ void k_lin(const float* __restrict__ lw, const float* __restrict__ lb,
                      float* __restrict__ out){
    int tid = blockIdx.x*blockDim.x + threadIdx.x;
    if (tid >= BATCH*NCLS) return;
    int c = tid % NCLS, b = tid / NCLS;
    float acc = lb[c];
    for (int f=0; f<F1; f++) acc += g_feat[b*F1+f]*lw[f*NCLS+c];
    out[tid] = acc;
}

// ================= host =================
extern "C" void kernel_launch(void* const* d_in, const int* in_sizes, int n_in,
                              void* d_out, int out_size){
    const float* x     = (const float*)d_in[0];
    const float* w_s2  = (const float*)d_in[1];
    const float* bn1g  = (const float*)d_in[3];
    const float* bn1b  = (const float*)d_in[4];
    const float* w_so3 = (const float*)d_in[5];
    const float* bn2g  = (const float*)d_in[7];
    const float* bn2b  = (const float*)d_in[8];
    const float* linw  = (const float*)d_in[9];
    const float* linb  = (const float*)d_in[10];
    float* out = (float*)d_out;

    k_setup<<<(TSETUP+255)/256,256>>>();                       // 1
    k_pre<<<PREGRID,256>>>(w_s2);                              // 2
    k_front<<<BATCH,256>>>(x);                                 // 3
    k_syn1<<<BATCH*F0,256>>>();                                // 4  <- profiled
    k_bnw<<<100 + (F0*F1*MR2+255)/256,256>>>(bn1g,bn1b,w_so3); // 5
    k_g2f<<<BATCH*F0,256>>>();                                 // 6
    k_z2<<<(BATCH*25*NH2+255)/256,256>>>();                    // 7
    k_syn2<<<BATCH*F1,256>>>();                                // 8
    k_bn2fin<<<F1,32>>>(bn2g, bn2b);                           // 9
    k_integrate<<<BATCH*F1,256>>>();                           // 10
    k_lin<<<(BATCH*NCLS+255)/256,256>>>(linw, linb, out);      // 11
}

// round 15
// speedup vs baseline: 1.5022x; 1.5022x over previous
#include <cuda_runtime.h>
#include <math.h>

#define PI 3.14159265358979323846

#define BATCH 8
#define NPTS  1024
#define F0    100
#define F1    100
#define NCLS  40

#define NA60  60
#define L1MAX 16
#define N32   32
#define L2MAX 10
#define N20   20

#define NC1   256
#define NH1   2856   // sum_{l<16} (l+1)(2l+1)
#define NH2   715    // sum_{l<10} (l+1)(2l+1)
#define NSQ2  1330   // sum_{l<10} (2l+1)^2
#define MR1   31
#define MR2   19

__device__ __forceinline__ int offsq(int l){ return l*(4*l*l-1)/3; }
__device__ __forceinline__ int hoff(int l){
    return ((l-1)*l*(2*l-1))/3 + (3*(l-1)*l)/2 + l;
}
__device__ __forceinline__ void unpack_h(int p, int &l, int &m, int &jn){
    l=0; while (p >= (l+1)*(2*l+1)){ p -= (l+1)*(2*l+1); l++; }
    m = p/(2*l+1); jn = p%(2*l+1);
}

// ---------------- scratch ----------------
__device__ float2 g_X1 [BATCH*NC1];
__device__ float2 g_Y1 [F0*NC1];
__device__ float  g_h1 [BATCH*F0*N32*N32*N32];
__device__ float  g_bn1a[F0], g_bn1bv[F0];
__device__ float2 g_Wh2[F0*F1*MR2];
__device__ float2 g_Aah[BATCH*F0*NH2];
__device__ float2 g_Z2h[BATCH*F1*NH2];
__device__ float  g_h2 [BATCH*F1*N20*N20*N20];
__device__ float  g_bn2a[F1], g_bn2bv[F1];
__device__ float  g_feat[BATCH*F1];
__device__ double2 g_s1p[BATCH*F0];
__device__ double2 g_s2p[BATCH*F1];

// ---------------- tables ----------------
__device__ float g_d16h  [N32*NH1];
__device__ float g_d10h  [N20*NH2];
__device__ float g_dh10  [NSQ2];
__device__ float g_dcol30[NA60*NC1];
__device__ float g_dhcol [NC1];
__device__ float g_qw30[NA60], g_qw16[N32], g_qw10[N20];

// ============ Wigner-d ============
__device__ double d_ipow(double x, int n){ double r=1.0; for(int i=0;i<n;i++) r*=x; return r; }

__device__ double d_wig(int l, int mp, int m, double beta, const double* f){
    if (l == 0) return 1.0;
    double cb = cos(0.5*beta), sb = sin(0.5*beta);
    int smin = max(0, m-mp);
    int smax = min(l+m, l-mp);
    double pref = sqrt(f[l+mp]*f[l-mp]*f[l+m]*f[l-m]);
    double term = d_ipow(cb, 2*l+m-mp-2*smin) * d_ipow(sb, mp-m+2*smin)
                / (f[l+m-smin]*f[smin]*f[mp-m+smin]*f[l-mp-smin]);
    if ((mp-m+smin)&1) term = -term;
    double acc = term;
    double r2 = (sb*sb)/(cb*cb);
    for (int s=smin; s<smax; s++){
        term *= -r2 * (double)((l+m-s)*(l-mp-s)) / ((double)(s+1)*(double)(mp-m+s+1));
        acc += term;
    }
    return pref*acc;
}

#define T0c (N32*NH1)
#define T1c (N20*NH2)
#define T2c (NSQ2)
#define T3c (NA60*NC1)
#define T4c (NC1)
#define T5c (112)
#define TSETUP (T0c+T1c+T2c+T3c+T4c+T5c)

__global__ void k_setup(){
    __shared__ double f[32];
    if (threadIdx.x == 0){ f[0]=1.0; for (int i=1;i<32;i++) f[i]=f[i-1]*(double)i; }
    __syncthreads();
    int tid = blockIdx.x*blockDim.x + threadIdx.x;
    if (tid >= TSETUP) return;
    if (tid < T0c){
        int k = tid/NH1;
        if (k >= 16) return;
        int p = tid%NH1;
        int l,m,jn; unpack_h(p,l,m,jn);
        double beta = PI*(2*k+1)/64.0;
        g_d16h[tid] = (float)d_wig(l, m, jn-l, beta, f);
        return;
    }
    tid -= T0c;
    if (tid < T1c){
        int k = tid/NH2;
        if (k >= 10) return;
        int p = tid%NH2;
        int l,m,jn; unpack_h(p,l,m,jn);
        double beta = PI*(2*k+1)/40.0;
        g_d10h[tid] = (float)d_wig(l, m, jn-l, beta, f);
        return;
    }
    tid -= T1c;
    if (tid < T2c){
        int p = tid;
        int l=0; while (p >= (2*l+1)*(2*l+1)){ p -= (2*l+1)*(2*l+1); l++; }
        int jm = p/(2*l+1), jn = p%(2*l+1);
        g_dh10[tid] = (float)d_wig(l, jm-l, jn-l, 0.5*PI, f);
        return;
    }
    tid -= T2c;
    if (tid < T3c){
        int k = tid/NC1;
        if (k >= 30) return;
        int p = tid%NC1;
        int l=0; while ((l+1)*(l+1) <= p) l++;
        int jm = p - l*l;
        double beta = PI*(2*k+1)/120.0;
        g_dcol30[tid] = (float)d_wig(l, jm-l, 0, beta, f);
        return;
    }
    tid -= T3c;
    if (tid < T4c){
        int p = tid;
        int l=0; while ((l+1)*(l+1) <= p) l++;
        int jm = p - l*l;
        g_dhcol[tid] = (float)d_wig(l, jm-l, 0, 0.5*PI, f);
        return;
    }
    tid -= T4c;
    {
        int bgrid, k; float* out;
        if (tid < 60){ bgrid=30; out=g_qw30; k=tid; }
        else if (tid < 92){ bgrid=16; out=g_qw16; k=tid-60; }
        else { bgrid=10; out=g_qw10; k=tid-92; }
        double beta = PI*(2*k+1)/(4.0*bgrid);
        double s = 0.0;
        for (int j=0;j<bgrid;j++)
            s += sin((double)(2*k+1)*(2*j+1)*PI/(4.0*bgrid))/(double)(2*j+1);
        out[k] = (float)((2.0/bgrid)*sin(beta)*s);
    }
}

// pre: blocks 0..99 = wh1+y1; blocks 100.. = table mirror
#define M0c (16*NH1)
#define M1c (10*NH2)
#define M3c (30*NC1)
#define MTOT (M0c+M1c+M3c)
#define PREGRID (100 + (MTOT+255)/256)

__global__ void k_pre(const float* __restrict__ w_s2){
    int t = threadIdx.x;
    if (blockIdx.x < 100){
        int o = blockIdx.x;
        __shared__ float2 tab[NA60];
        __shared__ float2 wh[MR1];
        if (t < NA60){ double s,c; sincospi(-2.0*t/60.0,&s,&c); tab[t]=make_float2((float)c,(float)s); }
        __syncthreads();
        if (t < MR1){
            int m = t - 15;
            int inc = ((m%60)+60)%60;
            float sr=0.0f, si=0.0f;
            const float* w = w_s2 + o*NA60;
            int idx=0;
            for (int p=0;p<NA60;p++){
                float2 e = tab[idx];
                sr += w[p]*e.x; si += w[p]*e.y;
                idx += inc; if (idx>=60) idx-=60;
            }
            wh[t] = make_float2(sr,si);
        }
        __syncthreads();
        {
            int p = t;
            int l=0; while ((l+1)*(l+1) <= p) l++;
            int m = (p - l*l) - l;
            float d = g_dhcol[p] * (1.0f/60.0f);
            float2 w = wh[m+15];
            g_Y1[o*NC1+p] = make_float2(d*w.x, d*w.y);
        }
        return;
    }
    int idx = (blockIdx.x-100)*256 + t;
    if (idx >= MTOT) return;
    if (idx < M0c){
        int kk = 16 + idx/NH1;
        int p = idx%NH1;
        int l,m,jn; unpack_h(p,l,m,jn);
        float v = g_d16h[(31-kk)*NH1 + p + 2*(l-jn)];
        g_d16h[kk*NH1 + p] = ((l+m)&1) ? -v : v;
        return;
    }
    idx -= M0c;
    if (idx < M1c){
        int kk = 10 + idx/NH2;
        int p = idx%NH2;
        int l,m,jn; unpack_h(p,l,m,jn);
        float v = g_d10h[(19-kk)*NH2 + p + 2*(l-jn)];
        g_d10h[kk*NH2 + p] = ((l+m)&1) ? -v : v;
        return;
    }
    idx -= M1c;
    {
        int kk = 30 + idx/NC1;
        int p = idx%NC1;
        int l=0; while ((l+1)*(l+1) <= p) l++;
        int jm = p - l*l;
        float v = g_dcol30[(59-kk)*NC1 + p];
        g_dcol30[kk*NC1 + p] = (jm&1) ? -v : v;
    }
}

// front: one block per batch
__global__ void k_front(const float* __restrict__ x){
    __shared__ float  img[NA60*NA60];
    __shared__ float2 Gas[NA60*MR1];
    __shared__ float2 tab[NA60];
    int b = blockIdx.x;
    int t = threadIdx.x;
    for (int i=t; i<NA60*NA60; i+=256) img[i]=0.0f;
    if (t < NA60){ double s,c; sincospi(-2.0*t/60.0,&s,&c); tab[t]=make_float2((float)c,(float)s); }
    __syncthreads();
    for (int p=t; p<NPTS; p+=256){
        float xx = x[b*3*NPTS + 0*NPTS + p];
        float yy = x[b*3*NPTS + 1*NPTS + p];
        float zz = x[b*3*NPTS + 2*NPTS + p];
        float r  = sqrtf(xx*xx + yy*yy + zz*zz);
        float rc = fmaxf(r, 1e-8f);
        float cz = fminf(fmaxf(zz/rc, -1.0f), 1.0f);
        float beta  = acosf(cz);
        float alpha = atan2f(yy, xx);
        if (alpha < 0.0f) alpha += 2.0f*(float)PI;
        int bi = (int)(beta/(float)PI*60.0f);          bi = min(max(bi,0),59);
        int ai = (int)(alpha/(2.0f*(float)PI)*60.0f);  ai = min(max(ai,0),59);
        atomicMax((int*)&img[bi*NA60+ai], __float_as_int(r));
    }
    __syncthreads();
    for (int e=t; e<NA60*MR1; e+=256){
        int j = e % MR1, k = e / MR1;
        int m = j - 15;
        int inc = ((m%60)+60)%60;
        float sr=0.0f, si=0.0f;
        const float* row = img + k*NA60;
        int idx=0;
        #pragma unroll 4
        for (int a=0;a<NA60;a++){
            float2 w = tab[idx];
            float v = row[a];
            sr += v*w.x; si += v*w.y;
            idx += inc; if (idx>=60) idx-=60;
        }
        Gas[e] = make_float2(sr,si);
    }
    __syncthreads();
    {
        int p = t;
        int l=0; while ((l+1)*(l+1) <= p) l++;
        int m = (p - l*l) - l;
        float ar=0.0f, ai=0.0f;
        for (int k=0;k<NA60;k++){
            float wd = g_qw30[k]*g_dcol30[k*NC1 + p];
            float2 ga = Gas[k*MR1 + (m+15)];
            ar += wd*ga.x; ai += wd*ga.y;
        }
        float sc = (float)(2.0*PI/60.0);
        g_X1[b*NC1+p] = make_float2(ar*sc, ai*sc);
    }
}

// layer-1 synthesis: merged M-build+fold (float4 PQ), T-stage, g-paired H-stage.
// Block per (b,o).
__global__ void k_syn1(){
    __shared__ float2 Zv [NH1];
    __shared__ float2 M0sh[16];
    __shared__ float4 PQ4[16*15];      // (Pr,Pi,Qr,Qi) for n=1..15
    __shared__ float2 Tsh[16*N32];
    __shared__ float2 Xsh[NC1], Ysh[NC1];
    __shared__ float2 ctab[N32];
    __shared__ double red[256], red2[256];
    int bo = blockIdx.x;
    int o = bo % F0, b = bo / F0;
    int t = threadIdx.x;
    for (int i=t;i<NC1;i+=256){ Xsh[i]=g_X1[b*NC1+i]; Ysh[i]=g_Y1[o*NC1+i]; }
    if (t < N32){ double s,c; sincospi(2.0*t/32.0,&s,&c); ctab[t]=make_float2((float)c,(float)s); }
    __syncthreads();
    for (int ph=t; ph<NH1; ph+=256){
        int l,m,jn; unpack_h(ph,l,m,jn);
        float2 xv = Xsh[l*l + m+l];
        float2 yv = Ysh[l*l + jn];
        float w = (float)(2*l+1);
        Zv[ph] = make_float2(w*(xv.x*yv.x + xv.y*yv.y),
                             w*(xv.y*yv.x - xv.x*yv.y));
    }
    double hs=0.0, dsq=0.0;
    float* hbase = g_h1 + (size_t)bo * 32768;
    const int m_ = t >> 4, n_ = t & 15;
    const int lmin_ = max(m_, n_);
    const int idx0_ = hoff(lmin_) + m_*(2*lmin_+1) + (n_+lmin_);
    const int d0_ = (lmin_+1)*(2*lmin_+1) + 2*m_ + 1;
    const int u0_ = 4*lmin_ + 5;
    const int n2_ = 2*n_;
    for (int k=0;k<N32;k++){
        __syncthreads();
        const float* dk = g_d16h + k*NH1;
        // ---- merged M-build + PQ-fold ----
        {
            int idx = idx0_, delta = d0_, upd = u0_;
            float arp=0.0f, aip=0.0f, arm=0.0f, aim=0.0f;
            for (int l=lmin_; l<L1MAX; l++){
                float wp = dk[idx];
                float2 zp = Zv[idx];
                arp = fmaf(wp, zp.x, arp); aip = fmaf(wp, zp.y, aip);
                int idm = idx - n2_;
                float wm = dk[idm];
                float2 zm = Zv[idm];
                arm = fmaf(wm, zm.x, arm); aim = fmaf(wm, zm.y, aim);
                idx += delta; delta += upd; upd += 4;
            }
            float w2 = (m_>0) ? 2.0f : 1.0f;
            if (n_ == 0){
                M0sh[m_] = make_float2(arp, aip);
                dsq += (double)(w2*(arp*arp + aip*aip));
                if (t == 0) hs += (double)arp;
            } else {
                PQ4[m_*15 + n_-1] = make_float4(arp+arm, aip+aim, arp-arm, aip-aim);
                dsq += (double)(w2*(arp*arp + aip*aip + arm*arm + aim*aim));
            }
        }
        __syncthreads();
        // ---- T-stage: float4 PQ loads ----
        for (int e=t; e<272; e+=256){
            int m = e/17, g = e%17;
            float2 M0 = M0sh[m];
            float tr1=M0.x, ti1=M0.y, tr2=M0.x, ti2=M0.y;
            int idx = g, step = g;
            #pragma unroll
            for (int n=1;n<16;n++){
                float2 w = ctab[idx];
                float4 q = PQ4[m*15 + n-1];      // (Pr,Pi,Qr,Qi)
                float pcx = q.x*w.x, pcy = q.y*w.x;
                float qsx = q.z*w.y, qsy = q.w*w.y;
                tr1 += pcx - qsy; ti1 += pcy + qsx;
                tr2 += pcx + qsy; ti2 += pcy - qsx;
                idx = (idx+step)&31;
            }
            float sc = (m>0) ? 2.0f : 1.0f;
            Tsh[m*N32+g] = make_float2(sc*tr1, sc*ti1);
            if (g!=0 && g!=16) Tsh[m*N32+32-g] = make_float2(sc*tr2, sc*ti2);
        }
        __syncthreads();
        // ---- H-stage: g-paired, one LDS.128 per (m, g-pair) ----
        float* hout = hbase + k*1024;
        for (int e=t; e<272; e+=256){
            int a = e >> 4, g0 = (e & 15) << 1;
            float4 t0 = *reinterpret_cast<const float4*>(&Tsh[g0]);   // m=0: (g0, g0+1)
            float acc1a = t0.x, acc2a = t0.x;
            float acc1b = t0.z, acc2b = t0.z;
            int idx = a, step = a;
            #pragma unroll
            for (int m=1;m<16;m++){
                float2 w = ctab[idx];
                float4 tv = *reinterpret_cast<const float4*>(&Tsh[m*N32+g0]);
                float p1a = tv.x*w.x, p2a = tv.y*w.y;
                acc1a += p1a - p2a; acc2a += p1a + p2a;
                float p1b = tv.z*w.x, p2b = tv.w*w.y;
                acc1b += p1b - p2b; acc2b += p1b + p2b;
                idx = (idx+step)&31;
            }
            *reinterpret_cast<float2*>(hout + a*32 + g0) = make_float2(acc1a, acc1b);
            if (a!=0 && a!=16)
                *reinterpret_cast<float2*>(hout + (32-a)*32 + g0) = make_float2(acc2a, acc2b);
        }
    }
    red[t]=hs; red2[t]=dsq; __syncthreads();
    for (int st=128; st>0; st>>=1){ if (t<st){ red[t]+=red[t+st]; red2[t]+=red2[t+st]; } __syncthreads(); }
    if (t==0) g_s1p[bo] = make_double2(1024.0*red[0], 1024.0*red2[0]);
}

// bnw: blocks 0..99 = bn1fin; blocks 100.. = wh2
__global__ void k_bnw(const float* __restrict__ gw, const float* __restrict__ gb,
                      const float* __restrict__ w_so3){
    int t = threadIdx.x;
    if (blockIdx.x < 100){
        int o = blockIdx.x;
        if (t >= 32) return;
        double s=0.0, s2=0.0;
        if (t < BATCH){ double2 p = g_s1p[t*F0+o]; s=p.x; s2=p.y; }
        for (int st=4; st>0; st>>=1){
            s  += __shfl_down_sync(0xffffffffu, s,  st);
            s2 += __shfl_down_sync(0xffffffffu, s2, st);
        }
        if (t==0){
            double N = (double)BATCH*32768.0;
            double mu = s/N;
            double var = s2/N - mu*mu;
            float a = gw[o] * (float)rsqrt(var + 1e-5);
            g_bn1a[o]=a; g_bn1bv[o]= gb[o] - (float)mu * a;
        }
        return;
    }
    __shared__ float2 tab[N32];
    if (t<N32){ double s,c; sincospi(-2.0*t/32.0,&s,&c); tab[t]=make_float2((float)c,(float)s); }
    __syncthreads();
    int tid = (blockIdx.x-100)*256 + t;
    if (tid >= F0*F1*MR2) return;
    int j = tid % MR2; int io = tid / MR2;
    int m = j - 9;
    int inc = m & 31;
    float sr=0.0f, si=0.0f;
    const float* w = w_so3 + io*N32;
    int idx=0;
    #pragma unroll
    for (int p=0;p<N32;p++){
        float2 e = tab[idx];
        sr += w[p]*e.x; si += w[p]*e.y;
        idx=(idx+inc)&31;
    }
    g_Wh2[tid] = make_float2(sr*(1.0f/32.0f), si*(1.0f/32.0f));
}

// fused BN+relu + half fft2 + beta-quadrature + pi/2 contraction. Block per (b,c).
__global__ void k_g2f(){
    __shared__ float  hsh[N32*N32];
    __shared__ float  Sph[15*N32], Smh[15*N32];
    __shared__ float2 Ush[10*N32];
    __shared__ float2 Gsh[10*MR2];
    __shared__ float2 ctab[N32];
    __shared__ float2 X2sh[NH2];
    int bc = blockIdx.x;
    int c = bc % F0;
    int t = threadIdx.x;
    float a1 = g_bn1a[c], b1 = g_bn1bv[c];
    if (t<N32){ double s,cc; sincospi(2.0*t/32.0,&s,&cc); ctab[t]=make_float2((float)cc,(float)s); }
    int pm[3], pcol[3];
    float axr[3]={0,0,0}, axi[3]={0,0,0};
    {
        int i=0;
        for (int p=t; p<NH2; p+=256){
            int l,m,jn; unpack_h(p,l,m,jn);
            pm[i]=m; pcol[i]=jn-l+9; i++;
        }
    }
    const float* hbase = g_h1 + (size_t)bc*32768;
    for (int k=0;k<N32;k++){
        __syncthreads();
        const float* hin = hbase + k*1024;
        for (int i=t;i<1024;i+=256){ float v = hin[i]*a1 + b1; hsh[i] = v>0.0f ? v : 0.0f; }
        __syncthreads();
        for (int e=t; e<480; e+=256){
            int a = e/32 + 1, g = e%32;
            float u = hsh[a*32+g], v = hsh[(32-a)*32+g];
            Sph[(a-1)*32+g] = u+v;
            Smh[(a-1)*32+g] = u-v;
        }
        __syncthreads();
        for (int e=t; e<320; e+=256){
            int m = e/32, g = e%32;
            float h16 = hsh[16*32+g];
            float ur = hsh[g] + ((m&1) ? -h16 : h16);
            float ui = 0.0f;
            int idx = m&31, step = m;
            #pragma unroll
            for (int a=1;a<16;a++){
                float2 w = ctab[idx];
                ur += Sph[(a-1)*32+g]*w.x;
                ui -= Smh[(a-1)*32+g]*w.y;
                idx = (idx+step)&31;
            }
            Ush[m*32+g] = make_float2(ur,ui);
        }
        __syncthreads();
        for (int e=t; e<100; e+=256){
            int m = e/10, n = e%10;
            float g1r=0,g1i=0,g2r=0,g2i=0;
            int idx=0;
            #pragma unroll 4
            for (int g=0; g<N32; g++){
                float2 w = ctab[idx];
                float2 u = Ush[m*32+g];
                float xc=u.x*w.x, ys=u.y*w.y, yc=u.y*w.x, xs=u.x*w.y;
                g1r += xc+ys; g1i += yc-xs;
                g2r += xc-ys; g2i += yc+xs;
                idx = (idx+n)&31;
            }
            Gsh[m*MR2 + 9+n] = make_float2(g1r,g1i);
            if (n) Gsh[m*MR2 + 9-n] = make_float2(g2r,g2i);
        }
        __syncthreads();
        {
            float qk = g_qw16[k];
            const float* dk = g_d16h + k*NH1;
            int i=0;
            for (int p=t; p<NH2; p+=256){
                float wd = qk*dk[p];
                float2 gg = Gsh[pm[i]*MR2 + pcol[i]];
                axr[i] += wd*gg.x; axi[i] += wd*gg.y; i++;
            }
        }
    }
    __syncthreads();
    {
        float sc = (float)((2.0*PI/32.0)*(2.0*PI/32.0));
        int i=0;
        for (int p=t; p<NH2; p+=256){ X2sh[p]=make_float2(axr[i]*sc, axi[i]*sc); i++; }
    }
    __syncthreads();
    float2* Aout = g_Aah + (size_t)bc*NH2;
    for (int p=t; p<NH2; p+=256){
        int l,m,jn; unpack_h(p,l,m,jn);
        int w = 2*l+1;
        const float2* X = X2sh + hoff(l) + m*w;
        const float*  dd = g_dh10 + offsq(l) + jn*w;
        float ar=0.0f, ai=0.0f;
        for (int jk=0; jk<w; jk++){ ar += dd[jk]*X[jk].x; ai += dd[jk]*X[jk].y; }
        Aout[p] = make_float2(ar,ai);
    }
}

// Z2 half with 4-way o tiling
__global__ void k_z2(){
    int tid = blockIdx.x*blockDim.x + threadIdx.x;
    if (tid >= BATCH*25*NH2) return;
    int p = tid % NH2; int rest = tid / NH2;
    int oq = rest % 25; int b = rest / 25;
    int l,m,jn; unpack_h(p,l,m,jn);
    int jw = (jn - l) + 9;
    float ar0=0,ai0=0,ar1=0,ai1=0,ar2=0,ai2=0,ar3=0,ai3=0;
    const float2* A = g_Aah + (size_t)b*F0*NH2 + p;
    const float2* W = g_Wh2 + oq*MR2 + jw;
    #pragma unroll 2
    for (int i=0;i<F0;i++){
        float2 a = A[(size_t)i*NH2];
        const float2* Wi = W + (size_t)i*F1*MR2;
        float2 w0 = Wi[0*25*MR2];
        float2 w1 = Wi[1*25*MR2];
        float2 w2 = Wi[2*25*MR2];
        float2 w3 = Wi[3*25*MR2];
        ar0 += a.x*w0.x + a.y*w0.y;  ai0 += a.y*w0.x - a.x*w0.y;
        ar1 += a.x*w1.x + a.y*w1.y;  ai1 += a.y*w1.x - a.x*w1.y;
        ar2 += a.x*w2.x + a.y*w2.y;  ai2 += a.y*w2.x - a.x*w2.y;
        ar3 += a.x*w3.x + a.y*w3.y;  ai3 += a.y*w3.x - a.x*w3.y;
    }
    size_t base = (size_t)(b*F1)*NH2 + p;
    g_Z2h[base + (size_t)(oq   )*NH2] = make_float2(ar0,ai0);
    g_Z2h[base + (size_t)(oq+25)*NH2] = make_float2(ar1,ai1);
    g_Z2h[base + (size_t)(oq+50)*NH2] = make_float2(ar2,ai2);
    g_Z2h[base + (size_t)(oq+75)*NH2] = make_float2(ar3,ai3);
}

// layer-2 synthesis: merged M-build+fold (float4 PQ), g-paired H. Block per (b,o).
__global__ void k_syn2(){
    __shared__ float2 Zsh[NH2];
    __shared__ float2 M0sh[10];
    __shared__ float4 PQ4[10*9];
    __shared__ float2 Tsh[10*N20];
    __shared__ float2 ctab[N20];
    __shared__ double red[256], red2[256];
    int bo = blockIdx.x;
    int t = threadIdx.x;
    if (t < N20){ double s,c; sincospi(2.0*t/20.0,&s,&c); ctab[t]=make_float2((float)c,(float)s); }
    for (int ph=t; ph<NH2; ph+=256){
        int l,m,jn; unpack_h(ph,l,m,jn);
        float2 z = g_Z2h[(size_t)bo*NH2 + ph];
        float w = (float)(2*l+1);
        Zsh[ph] = make_float2(w*z.x, w*z.y);
    }
    double hs=0.0, dsq=0.0;
    float* hbase = g_h2 + (size_t)bo*8000;
    int m_=0, n_=0, lmin_=0, idx0_=0, d0_=0, u0_=0, n2_=0;
    if (t < 100){
        m_ = t/10; n_ = t%10;
        lmin_ = max(m_, n_);
        idx0_ = hoff(lmin_) + m_*(2*lmin_+1) + (n_+lmin_);
        d0_ = (lmin_+1)*(2*lmin_+1) + 2*m_ + 1;
        u0_ = 4*lmin_ + 5;
        n2_ = 2*n_;
    }
    for (int k=0;k<N20;k++){
        __syncthreads();
        const float* dk = g_d10h + k*NH2;
        if (t < 100){
            int idx = idx0_, delta = d0_, upd = u0_;
            float arp=0.0f, aip=0.0f, arm=0.0f, aim=0.0f;
            for (int l=lmin_; l<L2MAX; l++){
                float wp = dk[idx];
                float2 zp = Zsh[idx];
                arp = fmaf(wp, zp.x, arp); aip = fmaf(wp, zp.y, aip);
                int idm = idx - n2_;
                float wm = dk[idm];
                float2 zm = Zsh[idm];
                arm = fmaf(wm, zm.x, arm); aim = fmaf(wm, zm.y, aim);
                idx += delta; delta += upd; upd += 4;
            }
            float w2 = (m_>0) ? 2.0f : 1.0f;
            if (n_ == 0){
                M0sh[m_] = make_float2(arp, aip);
                dsq += (double)(w2*(arp*arp + aip*aip));
                if (t == 0) hs += (double)arp;
            } else {
                PQ4[m_*9 + n_-1] = make_float4(arp+arm, aip+aim, arp-arm, aip-aim);
                dsq += (double)(w2*(arp*arp + aip*aip + arm*arm + aim*aim));
            }
        }
        __syncthreads();
        for (int e=t; e<110; e+=256){
            int m = e/11, g = e%11;
            float2 M0 = M0sh[m];
            float tr1=M0.x, ti1=M0.y, tr2=M0.x, ti2=M0.y;
            int idx = g, step = g;
            #pragma unroll
            for (int n=1;n<10;n++){
                float2 w = ctab[idx];
                float4 q = PQ4[m*9 + n-1];
                float pcx = q.x*w.x, pcy = q.y*w.x;
                float qsx = q.z*w.y, qsy = q.w*w.y;
                tr1 += pcx - qsy; ti1 += pcy + qsx;
                tr2 += pcx + qsy; ti2 += pcy - qsx;
                idx += step; if (idx>=20) idx-=20;
            }
            float sc = (m>0) ? 2.0f : 1.0f;
            Tsh[m*N20+g] = make_float2(sc*tr1, sc*ti1);
            if (g!=0 && g!=10) Tsh[m*N20+20-g] = make_float2(sc*tr2, sc*ti2);
        }
        __syncthreads();
        // H-stage: g-paired (a 0..10, g-pair 0..9)
        float* hout = hbase + k*400;
        for (int e=t; e<110; e+=256){
            int a = e/10, g0 = (e%10)*2;
            float4 t0 = *reinterpret_cast<const float4*>(&Tsh[g0]);
            float acc1a = t0.x, acc2a = t0.x;
            float acc1b = t0.z, acc2b = t0.z;
            int idx = a, step = a;
            #pragma unroll
            for (int m=1;m<10;m++){
                float2 w = ctab[idx];
                float4 tv = *reinterpret_cast<const float4*>(&Tsh[m*N20+g0]);
                float p1a = tv.x*w.x, p2a = tv.y*w.y;
                acc1a += p1a - p2a; acc2a += p1a + p2a;
                float p1b = tv.z*w.x, p2b = tv.w*w.y;
                acc1b += p1b - p2b; acc2b += p1b + p2b;
                idx += step; if (idx>=20) idx-=20;
            }
            *reinterpret_cast<float2*>(hout + a*20 + g0) = make_float2(acc1a, acc1b);
            if (a!=0 && a!=10)
                *reinterpret_cast<float2*>(hout + (20-a)*20 + g0) = make_float2(acc2a, acc2b);
        }
    }
    red[t]=hs; red2[t]=dsq; __syncthreads();
    for (int st=128; st>0; st>>=1){ if (t<st){ red[t]+=red[t+st]; red2[t]+=red2[t+st]; } __syncthreads(); }
    if (t==0) g_s2p[bo] = make_double2(400.0*red[0], 400.0*red2[0]);
}

__global__ void k_bn2fin(const float* __restrict__ gw, const float* __restrict__ gb){
    int o = blockIdx.x; int t = threadIdx.x;
    double s=0.0, s2=0.0;
    if (t < BATCH){ double2 p = g_s2p[t*F1+o]; s=p.x; s2=p.y; }
    for (int st=4; st>0; st>>=1){
        s  += __shfl_down_sync(0xffffffffu, s,  st);
        s2 += __shfl_down_sync(0xffffffffu, s2, st);
    }
    if (t==0){
        double N = (double)BATCH*8000.0;
        double mu = s/N;
        double var = s2/N - mu*mu;
        float a = gw[o] * (float)rsqrt(var + 1e-5);
        g_bn2a[o]=a; g_bn2bv[o]= gb[o] - (float)mu * a;
    }
}

__global__ void k_integrate(){
    int bf = blockIdx.x;
    int f = bf % F1;
    int t = threadIdx.x;
    float a = g_bn2a[f], bb = g_bn2bv[f];
    double s = 0.0;
    const float* h = g_h2 + (size_t)bf*8000;
    for (int idx=t; idx<8000; idx+=256){
        int k = idx/400;
        float v = h[idx]*a + bb;
        v = v>0.0f ? v : 0.0f;
        s += (double)v * (double)g_qw10[k];
    }
    __shared__ double sh[256];
    sh[t]=s; __syncthreads();
    for (int st=128; st>0; st>>=1){ if (t<st) sh[t]+=sh[t+st]; __syncthreads(); }
    if (t==0){
        double sc = (2.0*PI/20.0)*(2.0*PI/20.0);
        g_feat[bf] = (float)(sh[0]*sc);
    }
}

__global__ void k_lin(const float* __restrict__ lw, const float* __restrict__ lb,
                      float* __restrict__ out){
    int tid = blockIdx.x*blockDim.x + threadIdx.x;
    if (tid >= BATCH*NCLS) return;
    int c = tid % NCLS, b = tid / NCLS;
    float acc = lb[c];
    for (int f=0; f<F1; f++) acc += g_feat[b*F1+f]*lw[f*NCLS+c];
    out[tid] = acc;
}

// ================= host =================
extern "C" void kernel_launch(void* const* d_in, const int* in_sizes, int n_in,
                              void* d_out, int out_size){
    const float* x     = (const float*)d_in[0];
    const float* w_s2  = (const float*)d_in[1];
    const float* bn1g  = (const float*)d_in[3];
    const float* bn1b  = (const float*)d_in[4];
    const float* w_so3 = (const float*)d_in[5];
    const float* bn2g  = (const float*)d_in[7];
    const float* bn2b  = (const float*)d_in[8];
    const float* linw  = (const float*)d_in[9];
    const float* linb  = (const float*)d_in[10];
    float* out = (float*)d_out;

    k_setup<<<(TSETUP+255)/256,256>>>();                       // 1
    k_pre<<<PREGRID,256>>>(w_s2);                              // 2
    k_front<<<BATCH,256>>>(x);                                 // 3
    k_syn1<<<BATCH*F0,256>>>();                                // 4  <- profiled
    k_bnw<<<100 + (F0*F1*MR2+255)/256,256>>>(bn1g,bn1b,w_so3); // 5
    k_g2f<<<BATCH*F0,256>>>();                                 // 6
    k_z2<<<(BATCH*25*NH2+255)/256,256>>>();                    // 7
    k_syn2<<<BATCH*F1,256>>>();                                // 8
    k_bn2fin<<<F1,32>>>(bn2g, bn2b);                           // 9
    k_integrate<<<BATCH*F1,256>>>();                           // 10
    k_lin<<<(BATCH*NCLS+255)/256,256>>>(linw, linb, out);      // 11
}

// round 16
// speedup vs baseline: 1.6374x; 1.0900x over previous
#include <cuda_runtime.h>
#include <math.h>

#define PI 3.14159265358979323846

#define BATCH 8
#define NPTS  1024
#define F0    100
#define F1    100
#define NCLS  40

#define NA60  60
#define L1MAX 16
#define N32   32
#define L2MAX 10
#define N20   20

#define NC1   256
#define NH1   2856   // sum_{l<16} (l+1)(2l+1)
#define NH2   715    // sum_{l<10} (l+1)(2l+1)
#define NSQ2  1330   // sum_{l<10} (2l+1)^2
#define MR1   31
#define MR2   19

__device__ __forceinline__ int offsq(int l){ return l*(4*l*l-1)/3; }
__device__ __forceinline__ int hoff(int l){
    return ((l-1)*l*(2*l-1))/3 + (3*(l-1)*l)/2 + l;
}
__device__ __forceinline__ void unpack_h(int p, int &l, int &m, int &jn){
    l=0; while (p >= (l+1)*(2*l+1)){ p -= (l+1)*(2*l+1); l++; }
    m = p/(2*l+1); jn = p%(2*l+1);
}

// ---------------- scratch ----------------
__device__ float2 g_X1 [BATCH*NC1];
__device__ float2 g_Y1 [F0*NC1];
__device__ float  g_h1 [BATCH*F0*N32*N32*N32];
__device__ float  g_bn1a[F0], g_bn1bv[F0];
__device__ float2 g_Wh2[F0*F1*MR2];
__device__ float2 g_Aah[BATCH*F0*NH2];
__device__ float2 g_Z2h[BATCH*F1*NH2];
__device__ float  g_h2 [BATCH*F1*N20*N20*N20];
__device__ float  g_bn2a[F1], g_bn2bv[F1];
__device__ float  g_feat[BATCH*F1];
__device__ double2 g_s1p[BATCH*F0];
__device__ double2 g_s2p[BATCH*F1];

// ---------------- tables ----------------
__device__ float g_d16h  [N32*NH1];
__device__ float g_d10h  [N20*NH2];
__device__ float g_dh10  [NSQ2];
__device__ float g_dcol30[NA60*NC1];
__device__ float g_dhcol [NC1];
__device__ float g_qw30[NA60], g_qw16[N32], g_qw10[N20];

// ============ Wigner-d ============
__device__ double d_ipow(double x, int n){ double r=1.0; for(int i=0;i<n;i++) r*=x; return r; }

__device__ double d_wig(int l, int mp, int m, double beta, const double* f){
    if (l == 0) return 1.0;
    double cb = cos(0.5*beta), sb = sin(0.5*beta);
    int smin = max(0, m-mp);
    int smax = min(l+m, l-mp);
    double pref = sqrt(f[l+mp]*f[l-mp]*f[l+m]*f[l-m]);
    double term = d_ipow(cb, 2*l+m-mp-2*smin) * d_ipow(sb, mp-m+2*smin)
                / (f[l+m-smin]*f[smin]*f[mp-m+smin]*f[l-mp-smin]);
    if ((mp-m+smin)&1) term = -term;
    double acc = term;
    double r2 = (sb*sb)/(cb*cb);
    for (int s=smin; s<smax; s++){
        term *= -r2 * (double)((l+m-s)*(l-mp-s)) / ((double)(s+1)*(double)(mp-m+s+1));
        acc += term;
    }
    return pref*acc;
}

#define T0c (N32*NH1)
#define T1c (N20*NH2)
#define T2c (NSQ2)
#define T3c (NA60*NC1)
#define T4c (NC1)
#define T5c (112)
#define TSETUP (T0c+T1c+T2c+T3c+T4c+T5c)

__global__ void k_setup(){
    __shared__ double f[32];
    if (threadIdx.x == 0){ f[0]=1.0; for (int i=1;i<32;i++) f[i]=f[i-1]*(double)i; }
    __syncthreads();
    int tid = blockIdx.x*blockDim.x + threadIdx.x;
    if (tid >= TSETUP) return;
    if (tid < T0c){
        int k = tid/NH1;
        if (k >= 16) return;
        int p = tid%NH1;
        int l,m,jn; unpack_h(p,l,m,jn);
        double beta = PI*(2*k+1)/64.0;
        g_d16h[tid] = (float)d_wig(l, m, jn-l, beta, f);
        return;
    }
    tid -= T0c;
    if (tid < T1c){
        int k = tid/NH2;
        if (k >= 10) return;
        int p = tid%NH2;
        int l,m,jn; unpack_h(p,l,m,jn);
        double beta = PI*(2*k+1)/40.0;
        g_d10h[tid] = (float)d_wig(l, m, jn-l, beta, f);
        return;
    }
    tid -= T1c;
    if (tid < T2c){
        int p = tid;
        int l=0; while (p >= (2*l+1)*(2*l+1)){ p -= (2*l+1)*(2*l+1); l++; }
        int jm = p/(2*l+1), jn = p%(2*l+1);
        g_dh10[tid] = (float)d_wig(l, jm-l, jn-l, 0.5*PI, f);
        return;
    }
    tid -= T2c;
    if (tid < T3c){
        int k = tid/NC1;
        if (k >= 30) return;
        int p = tid%NC1;
        int l=0; while ((l+1)*(l+1) <= p) l++;
        int jm = p - l*l;
        double beta = PI*(2*k+1)/120.0;
        g_dcol30[tid] = (float)d_wig(l, jm-l, 0, beta, f);
        return;
    }
    tid -= T3c;
    if (tid < T4c){
        int p = tid;
        int l=0; while ((l+1)*(l+1) <= p) l++;
        int jm = p - l*l;
        g_dhcol[tid] = (float)d_wig(l, jm-l, 0, 0.5*PI, f);
        return;
    }
    tid -= T4c;
    {
        int bgrid, k; float* out;
        if (tid < 60){ bgrid=30; out=g_qw30; k=tid; }
        else if (tid < 92){ bgrid=16; out=g_qw16; k=tid-60; }
        else { bgrid=10; out=g_qw10; k=tid-92; }
        double beta = PI*(2*k+1)/(4.0*bgrid);
        double s = 0.0;
        for (int j=0;j<bgrid;j++)
            s += sin((double)(2*k+1)*(2*j+1)*PI/(4.0*bgrid))/(double)(2*j+1);
        out[k] = (float)((2.0/bgrid)*sin(beta)*s);
    }
}

// pre: blocks 0..99 = wh1+y1; blocks 100.. = table mirror
#define M0c (16*NH1)
#define M1c (10*NH2)
#define M3c (30*NC1)
#define MTOT (M0c+M1c+M3c)
#define PREGRID (100 + (MTOT+255)/256)

__global__ void k_pre(const float* __restrict__ w_s2){
    int t = threadIdx.x;
    if (blockIdx.x < 100){
        int o = blockIdx.x;
        __shared__ float2 tab[NA60];
        __shared__ float2 wh[MR1];
        if (t < NA60){ double s,c; sincospi(-2.0*t/60.0,&s,&c); tab[t]=make_float2((float)c,(float)s); }
        __syncthreads();
        if (t < MR1){
            int m = t - 15;
            int inc = ((m%60)+60)%60;
            float sr=0.0f, si=0.0f;
            const float* w = w_s2 + o*NA60;
            int idx=0;
            for (int p=0;p<NA60;p++){
                float2 e = tab[idx];
                sr += w[p]*e.x; si += w[p]*e.y;
                idx += inc; if (idx>=60) idx-=60;
            }
            wh[t] = make_float2(sr,si);
        }
        __syncthreads();
        {
            int p = t;
            int l=0; while ((l+1)*(l+1) <= p) l++;
            int m = (p - l*l) - l;
            float d = g_dhcol[p] * (1.0f/60.0f);
            float2 w = wh[m+15];
            g_Y1[o*NC1+p] = make_float2(d*w.x, d*w.y);
        }
        return;
    }
    int idx = (blockIdx.x-100)*256 + t;
    if (idx >= MTOT) return;
    if (idx < M0c){
        int kk = 16 + idx/NH1;
        int p = idx%NH1;
        int l,m,jn; unpack_h(p,l,m,jn);
        float v = g_d16h[(31-kk)*NH1 + p + 2*(l-jn)];
        g_d16h[kk*NH1 + p] = ((l+m)&1) ? -v : v;
        return;
    }
    idx -= M0c;
    if (idx < M1c){
        int kk = 10 + idx/NH2;
        int p = idx%NH2;
        int l,m,jn; unpack_h(p,l,m,jn);
        float v = g_d10h[(19-kk)*NH2 + p + 2*(l-jn)];
        g_d10h[kk*NH2 + p] = ((l+m)&1) ? -v : v;
        return;
    }
    idx -= M1c;
    {
        int kk = 30 + idx/NC1;
        int p = idx%NC1;
        int l=0; while ((l+1)*(l+1) <= p) l++;
        int jm = p - l*l;
        float v = g_dcol30[(59-kk)*NC1 + p];
        g_dcol30[kk*NC1 + p] = (jm&1) ? -v : v;
    }
}

// front: one block per batch
__global__ void k_front(const float* __restrict__ x){
    __shared__ float  img[NA60*NA60];
    __shared__ float2 Gas[NA60*MR1];
    __shared__ float2 tab[NA60];
    int b = blockIdx.x;
    int t = threadIdx.x;
    for (int i=t; i<NA60*NA60; i+=256) img[i]=0.0f;
    if (t < NA60){ double s,c; sincospi(-2.0*t/60.0,&s,&c); tab[t]=make_float2((float)c,(float)s); }
    __syncthreads();
    for (int p=t; p<NPTS; p+=256){
        float xx = x[b*3*NPTS + 0*NPTS + p];
        float yy = x[b*3*NPTS + 1*NPTS + p];
        float zz = x[b*3*NPTS + 2*NPTS + p];
        float r  = sqrtf(xx*xx + yy*yy + zz*zz);
        float rc = fmaxf(r, 1e-8f);
        float cz = fminf(fmaxf(zz/rc, -1.0f), 1.0f);
        float beta  = acosf(cz);
        float alpha = atan2f(yy, xx);
        if (alpha < 0.0f) alpha += 2.0f*(float)PI;
        int bi = (int)(beta/(float)PI*60.0f);          bi = min(max(bi,0),59);
        int ai = (int)(alpha/(2.0f*(float)PI)*60.0f);  ai = min(max(ai,0),59);
        atomicMax((int*)&img[bi*NA60+ai], __float_as_int(r));
    }
    __syncthreads();
    for (int e=t; e<NA60*MR1; e+=256){
        int j = e % MR1, k = e / MR1;
        int m = j - 15;
        int inc = ((m%60)+60)%60;
        float sr=0.0f, si=0.0f;
        const float* row = img + k*NA60;
        int idx=0;
        #pragma unroll 4
        for (int a=0;a<NA60;a++){
            float2 w = tab[idx];
            float v = row[a];
            sr += v*w.x; si += v*w.y;
            idx += inc; if (idx>=60) idx-=60;
        }
        Gas[e] = make_float2(sr,si);
    }
    __syncthreads();
    {
        int p = t;
        int l=0; while ((l+1)*(l+1) <= p) l++;
        int m = (p - l*l) - l;
        float ar=0.0f, ai=0.0f;
        for (int k=0;k<NA60;k++){
            float wd = g_qw30[k]*g_dcol30[k*NC1 + p];
            float2 ga = Gas[k*MR1 + (m+15)];
            ar += wd*ga.x; ai += wd*ga.y;
        }
        float sc = (float)(2.0*PI/60.0);
        g_X1[b*NC1+p] = make_float2(ar*sc, ai*sc);
    }
}

// layer-1 synthesis (R13 version): merged M-build+fold into float4 PQ, scalar H.
// Block per (b,o).
__global__ void k_syn1(){
    __shared__ float2 Zv [NH1];
    __shared__ float2 M0sh[16];
    __shared__ float4 PQ4[16*15];      // (Pr,Pi,Qr,Qi) for n=1..15
    __shared__ float2 Tsh[16*N32];
    __shared__ float2 Xsh[NC1], Ysh[NC1];
    __shared__ float2 ctab[N32];
    __shared__ double red[256], red2[256];
    int bo = blockIdx.x;
    int o = bo % F0, b = bo / F0;
    int t = threadIdx.x;
    for (int i=t;i<NC1;i+=256){ Xsh[i]=g_X1[b*NC1+i]; Ysh[i]=g_Y1[o*NC1+i]; }
    if (t < N32){ double s,c; sincospi(2.0*t/32.0,&s,&c); ctab[t]=make_float2((float)c,(float)s); }
    __syncthreads();
    for (int ph=t; ph<NH1; ph+=256){
        int l,m,jn; unpack_h(ph,l,m,jn);
        float2 xv = Xsh[l*l + m+l];
        float2 yv = Ysh[l*l + jn];
        float w = (float)(2*l+1);
        Zv[ph] = make_float2(w*(xv.x*yv.x + xv.y*yv.y),
                             w*(xv.y*yv.x - xv.x*yv.y));
    }
    double hs=0.0, dsq=0.0;
    float* hbase = g_h1 + (size_t)bo * 32768;
    const int m_ = t >> 4, n_ = t & 15;
    const int lmin_ = max(m_, n_);
    const int idx0_ = hoff(lmin_) + m_*(2*lmin_+1) + (n_+lmin_);
    const int d0_ = (lmin_+1)*(2*lmin_+1) + 2*m_ + 1;
    const int u0_ = 4*lmin_ + 5;
    const int n2_ = 2*n_;
    for (int k=0;k<N32;k++){
        __syncthreads();
        const float* dk = g_d16h + k*NH1;
        // ---- merged M-build + PQ-fold ----
        {
            int idx = idx0_, delta = d0_, upd = u0_;
            float arp=0.0f, aip=0.0f, arm=0.0f, aim=0.0f;
            for (int l=lmin_; l<L1MAX; l++){
                float wp = dk[idx];
                float2 zp = Zv[idx];
                arp = fmaf(wp, zp.x, arp); aip = fmaf(wp, zp.y, aip);
                int idm = idx - n2_;
                float wm = dk[idm];
                float2 zm = Zv[idm];
                arm = fmaf(wm, zm.x, arm); aim = fmaf(wm, zm.y, aim);
                idx += delta; delta += upd; upd += 4;
            }
            float w2 = (m_>0) ? 2.0f : 1.0f;
            if (n_ == 0){
                M0sh[m_] = make_float2(arp, aip);
                dsq += (double)(w2*(arp*arp + aip*aip));
                if (t == 0) hs += (double)arp;
            } else {
                PQ4[m_*15 + n_-1] = make_float4(arp+arm, aip+aim, arp-arm, aip-aim);
                dsq += (double)(w2*(arp*arp + aip*aip + arm*arm + aim*aim));
            }
        }
        __syncthreads();
        // ---- T-stage: float4 PQ loads ----
        for (int e=t; e<272; e+=256){
            int m = e/17, g = e%17;
            float2 M0 = M0sh[m];
            float tr1=M0.x, ti1=M0.y, tr2=M0.x, ti2=M0.y;
            int idx = g, step = g;
            #pragma unroll
            for (int n=1;n<16;n++){
                float2 w = ctab[idx];
                float4 q = PQ4[m*15 + n-1];      // (Pr,Pi,Qr,Qi)
                float pcx = q.x*w.x, pcy = q.y*w.x;
                float qsx = q.z*w.y, qsy = q.w*w.y;
                tr1 += pcx - qsy; ti1 += pcy + qsx;
                tr2 += pcx + qsy; ti2 += pcy - qsx;
                idx = (idx+step)&31;
            }
            float sc = (m>0) ? 2.0f : 1.0f;
            Tsh[m*N32+g] = make_float2(sc*tr1, sc*ti1);
            if (g!=0 && g!=16) Tsh[m*N32+32-g] = make_float2(sc*tr2, sc*ti2);
        }
        __syncthreads();
        // ---- H-stage (scalar, R13) ----
        float* hout = hbase + k*1024;
        for (int e=t; e<544; e+=256){
            int a = e >> 5, g = e & 31;
            float acc1 = Tsh[g].x, acc2 = acc1;
            int idx = a, step = a;
            #pragma unroll
            for (int m=1;m<16;m++){
                float2 w = ctab[idx];
                float2 tv = Tsh[m*N32+g];
                float p1 = tv.x*w.x, p2 = tv.y*w.y;
                acc1 += p1 - p2;
                acc2 += p1 + p2;
                idx = (idx+step)&31;
            }
            hout[a*32+g] = acc1;
            if (a!=0 && a!=16) hout[(32-a)*32+g] = acc2;
        }
    }
    red[t]=hs; red2[t]=dsq; __syncthreads();
    for (int st=128; st>0; st>>=1){ if (t<st){ red[t]+=red[t+st]; red2[t]+=red2[t+st]; } __syncthreads(); }
    if (t==0) g_s1p[bo] = make_double2(1024.0*red[0], 1024.0*red2[0]);
}

// bnw: blocks 0..99 = bn1fin; blocks 100.. = wh2
__global__ void k_bnw(const float* __restrict__ gw, const float* __restrict__ gb,
                      const float* __restrict__ w_so3){
    int t = threadIdx.x;
    if (blockIdx.x < 100){
        int o = blockIdx.x;
        if (t >= 32) return;
        double s=0.0, s2=0.0;
        if (t < BATCH){ double2 p = g_s1p[t*F0+o]; s=p.x; s2=p.y; }
        for (int st=4; st>0; st>>=1){
            s  += __shfl_down_sync(0xffffffffu, s,  st);
            s2 += __shfl_down_sync(0xffffffffu, s2, st);
        }
        if (t==0){
            double N = (double)BATCH*32768.0;
            double mu = s/N;
            double var = s2/N - mu*mu;
            float a = gw[o] * (float)rsqrt(var + 1e-5);
            g_bn1a[o]=a; g_bn1bv[o]= gb[o] - (float)mu * a;
        }
        return;
    }
    __shared__ float2 tab[N32];
    if (t<N32){ double s,c; sincospi(-2.0*t/32.0,&s,&c); tab[t]=make_float2((float)c,(float)s); }
    __syncthreads();
    int tid = (blockIdx.x-100)*256 + t;
    if (tid >= F0*F1*MR2) return;
    int j = tid % MR2; int io = tid / MR2;
    int m = j - 9;
    int inc = m & 31;
    float sr=0.0f, si=0.0f;
    const float* w = w_so3 + io*N32;
    int idx=0;
    #pragma unroll
    for (int p=0;p<N32;p++){
        float2 e = tab[idx];
        sr += w[p]*e.x; si += w[p]*e.y;
        idx=(idx+inc)&31;
    }
    g_Wh2[tid] = make_float2(sr*(1.0f/32.0f), si*(1.0f/32.0f));
}

// fused BN+relu+fold on load + half fft2 + beta-quadrature + pi/2 contraction.
// Block per (b,c).
__global__ void k_g2f(){
    __shared__ float  h0sh[N32], h16sh[N32];
    __shared__ float  Sph[15*N32], Smh[15*N32];
    __shared__ float2 Ush[10*N32];
    __shared__ float2 Gsh[10*MR2];
    __shared__ float2 ctab[N32];
    __shared__ float2 X2sh[NH2];
    int bc = blockIdx.x;
    int c = bc % F0;
    int t = threadIdx.x;
    float a1 = g_bn1a[c], b1 = g_bn1bv[c];
    if (t<N32){ double s,cc; sincospi(2.0*t/32.0,&s,&cc); ctab[t]=make_float2((float)cc,(float)s); }
    int pm[3], pcol[3];
    float axr[3]={0,0,0}, axi[3]={0,0,0};
    {
        int i=0;
        for (int p=t; p<NH2; p+=256){
            int l,m,jn; unpack_h(p,l,m,jn);
            pm[i]=m; pcol[i]=jn-l+9; i++;
        }
    }
    const float* hbase = g_h1 + (size_t)bc*32768;
    for (int k=0;k<N32;k++){
        __syncthreads();
        const float* hin = hbase + k*1024;
        // ---- load + BN + relu + a-fold in one pass (544 items: a=0..16, g) ----
        for (int e=t; e<544; e+=256){
            int a = e >> 5, g = e & 31;
            if (a == 0){
                float v = hin[g]*a1 + b1; h0sh[g] = v>0.0f ? v : 0.0f;
            } else if (a == 16){
                float v = hin[16*32+g]*a1 + b1; h16sh[g] = v>0.0f ? v : 0.0f;
            } else {
                float u = hin[a*32+g]*a1 + b1;      u = u>0.0f ? u : 0.0f;
                float v = hin[(32-a)*32+g]*a1 + b1; v = v>0.0f ? v : 0.0f;
                Sph[(a-1)*32+g] = u+v;
                Smh[(a-1)*32+g] = u-v;
            }
        }
        __syncthreads();
        for (int e=t; e<320; e+=256){
            int m = e/32, g = e%32;
            float h16 = h16sh[g];
            float ur = h0sh[g] + ((m&1) ? -h16 : h16);
            float ui = 0.0f;
            int idx = m&31, step = m;
            #pragma unroll
            for (int a=1;a<16;a++){
                float2 w = ctab[idx];
                ur += Sph[(a-1)*32+g]*w.x;
                ui -= Smh[(a-1)*32+g]*w.y;
                idx = (idx+step)&31;
            }
            Ush[m*32+g] = make_float2(ur,ui);
        }
        __syncthreads();
        for (int e=t; e<100; e+=256){
            int m = e/10, n = e%10;
            float g1r=0,g1i=0,g2r=0,g2i=0;
            int idx=0;
            #pragma unroll 4
            for (int g=0; g<N32; g++){
                float2 w = ctab[idx];
                float2 u = Ush[m*32+g];
                float xc=u.x*w.x, ys=u.y*w.y, yc=u.y*w.x, xs=u.x*w.y;
                g1r += xc+ys; g1i += yc-xs;
                g2r += xc-ys; g2i += yc+xs;
                idx = (idx+n)&31;
            }
            Gsh[m*MR2 + 9+n] = make_float2(g1r,g1i);
            if (n) Gsh[m*MR2 + 9-n] = make_float2(g2r,g2i);
        }
        __syncthreads();
        {
            float qk = g_qw16[k];
            const float* dk = g_d16h + k*NH1;
            int i=0;
            for (int p=t; p<NH2; p+=256){
                float wd = qk*dk[p];
                float2 gg = Gsh[pm[i]*MR2 + pcol[i]];
                axr[i] += wd*gg.x; axi[i] += wd*gg.y; i++;
            }
        }
    }
    __syncthreads();
    {
        float sc = (float)((2.0*PI/32.0)*(2.0*PI/32.0));
        int i=0;
        for (int p=t; p<NH2; p+=256){ X2sh[p]=make_float2(axr[i]*sc, axi[i]*sc); i++; }
    }
    __syncthreads();
    float2* Aout = g_Aah + (size_t)bc*NH2;
    for (int p=t; p<NH2; p+=256){
        int l,m,jn; unpack_h(p,l,m,jn);
        int w = 2*l+1;
        const float2* X = X2sh + hoff(l) + m*w;
        const float*  dd = g_dh10 + offsq(l) + jn*w;
        float ar=0.0f, ai=0.0f;
        for (int jk=0; jk<w; jk++){ ar += dd[jk]*X[jk].x; ai += dd[jk]*X[jk].y; }
        Aout[p] = make_float2(ar,ai);
    }
}

// Z2 half with 4-way o tiling
__global__ void k_z2(){
    int tid = blockIdx.x*blockDim.x + threadIdx.x;
    if (tid >= BATCH*25*NH2) return;
    int p = tid % NH2; int rest = tid / NH2;
    int oq = rest % 25; int b = rest / 25;
    int l,m,jn; unpack_h(p,l,m,jn);
    int jw = (jn - l) + 9;
    float ar0=0,ai0=0,ar1=0,ai1=0,ar2=0,ai2=0,ar3=0,ai3=0;
    const float2* A = g_Aah + (size_t)b*F0*NH2 + p;
    const float2* W = g_Wh2 + oq*MR2 + jw;
    #pragma unroll 2
    for (int i=0;i<F0;i++){
        float2 a = A[(size_t)i*NH2];
        const float2* Wi = W + (size_t)i*F1*MR2;
        float2 w0 = Wi[0*25*MR2];
        float2 w1 = Wi[1*25*MR2];
        float2 w2 = Wi[2*25*MR2];
        float2 w3 = Wi[3*25*MR2];
        ar0 += a.x*w0.x + a.y*w0.y;  ai0 += a.y*w0.x - a.x*w0.y;
        ar1 += a.x*w1.x + a.y*w1.y;  ai1 += a.y*w1.x - a.x*w1.y;
        ar2 += a.x*w2.x + a.y*w2.y;  ai2 += a.y*w2.x - a.x*w2.y;
        ar3 += a.x*w3.x + a.y*w3.y;  ai3 += a.y*w3.x - a.x*w3.y;
    }
    size_t base = (size_t)(b*F1)*NH2 + p;
    g_Z2h[base + (size_t)(oq   )*NH2] = make_float2(ar0,ai0);
    g_Z2h[base + (size_t)(oq+25)*NH2] = make_float2(ar1,ai1);
    g_Z2h[base + (size_t)(oq+50)*NH2] = make_float2(ar2,ai2);
    g_Z2h[base + (size_t)(oq+75)*NH2] = make_float2(ar3,ai3);
}

// layer-2 synthesis (R13 version): merged M-build+fold (float4 PQ), scalar H.
// Block per (b,o).
__global__ void k_syn2(){
    __shared__ float2 Zsh[NH2];
    __shared__ float2 M0sh[10];
    __shared__ float4 PQ4[10*9];
    __shared__ float2 Tsh[10*N20];
    __shared__ float2 ctab[N20];
    __shared__ double red[256], red2[256];
    int bo = blockIdx.x;
    int t = threadIdx.x;
    if (t < N20){ double s,c; sincospi(2.0*t/20.0,&s,&c); ctab[t]=make_float2((float)c,(float)s); }
    for (int ph=t; ph<NH2; ph+=256){
        int l,m,jn; unpack_h(ph,l,m,jn);
        float2 z = g_Z2h[(size_t)bo*NH2 + ph];
        float w = (float)(2*l+1);
        Zsh[ph] = make_float2(w*z.x, w*z.y);
    }
    double hs=0.0, dsq=0.0;
    float* hbase = g_h2 + (size_t)bo*8000;
    int m_=0, n_=0, lmin_=0, idx0_=0, d0_=0, u0_=0, n2_=0;
    if (t < 100){
        m_ = t/10; n_ = t%10;
        lmin_ = max(m_, n_);
        idx0_ = hoff(lmin_) + m_*(2*lmin_+1) + (n_+lmin_);
        d0_ = (lmin_+1)*(2*lmin_+1) + 2*m_ + 1;
        u0_ = 4*lmin_ + 5;
        n2_ = 2*n_;
    }
    for (int k=0;k<N20;k++){
        __syncthreads();
        const float* dk = g_d10h + k*NH2;
        if (t < 100){
            int idx = idx0_, delta = d0_, upd = u0_;
            float arp=0.0f, aip=0.0f, arm=0.0f, aim=0.0f;
            for (int l=lmin_; l<L2MAX; l++){
                float wp = dk[idx];
                float2 zp = Zsh[idx];
                arp = fmaf(wp, zp.x, arp); aip = fmaf(wp, zp.y, aip);
                int idm = idx - n2_;
                float wm = dk[idm];
                float2 zm = Zsh[idm];
                arm = fmaf(wm, zm.x, arm); aim = fmaf(wm, zm.y, aim);
                idx += delta; delta += upd; upd += 4;
            }
            float w2 = (m_>0) ? 2.0f : 1.0f;
            if (n_ == 0){
                M0sh[m_] = make_float2(arp, aip);
                dsq += (double)(w2*(arp*arp + aip*aip));
                if (t == 0) hs += (double)arp;
            } else {
                PQ4[m_*9 + n_-1] = make_float4(arp+arm, aip+aim, arp-arm, aip-aim);
                dsq += (double)(w2*(arp*arp + aip*aip + arm*arm + aim*aim));
            }
        }
        __syncthreads();
        for (int e=t; e<110; e+=256){
            int m = e/11, g = e%11;
            float2 M0 = M0sh[m];
            float tr1=M0.x, ti1=M0.y, tr2=M0.x, ti2=M0.y;
            int idx = g, step = g;
            #pragma unroll
            for (int n=1;n<10;n++){
                float2 w = ctab[idx];
                float4 q = PQ4[m*9 + n-1];
                float pcx = q.x*w.x, pcy = q.y*w.x;
                float qsx = q.z*w.y, qsy = q.w*w.y;
                tr1 += pcx - qsy; ti1 += pcy + qsx;
                tr2 += pcx + qsy; ti2 += pcy - qsx;
                idx += step; if (idx>=20) idx-=20;
            }
            float sc = (m>0) ? 2.0f : 1.0f;
            Tsh[m*N20+g] = make_float2(sc*tr1, sc*ti1);
            if (g!=0 && g!=10) Tsh[m*N20+20-g] = make_float2(sc*tr2, sc*ti2);
        }
        __syncthreads();
        float* hout = hbase + k*400;
        for (int e=t; e<220; e+=256){
            int a = e/20, g = e%20;
            float acc1 = Tsh[g].x, acc2 = acc1;
            int idx = a, step = a;
            #pragma unroll
            for (int m=1;m<10;m++){
                float2 w = ctab[idx];
                float2 tv = Tsh[m*N20+g];
                float p1 = tv.x*w.x, p2 = tv.y*w.y;
                acc1 += p1 - p2;
                acc2 += p1 + p2;
                idx += step; if (idx>=20) idx-=20;
            }
            hout[a*20+g] = acc1;
            if (a!=0 && a!=10) hout[(20-a)*20+g] = acc2;
        }
    }
    red[t]=hs; red2[t]=dsq; __syncthreads();
    for (int st=128; st>0; st>>=1){ if (t<st){ red[t]+=red[t+st]; red2[t]+=red2[t+st]; } __syncthreads(); }
    if (t==0) g_s2p[bo] = make_double2(400.0*red[0], 400.0*red2[0]);
}

__global__ void k_bn2fin(const float* __restrict__ gw, const float* __restrict__ gb){
    int o = blockIdx.x; int t = threadIdx.x;
    double s=0.0, s2=0.0;
    if (t < BATCH){ double2 p = g_s2p[t*F1+o]; s=p.x; s2=p.y; }
    for (int st=4; st>0; st>>=1){
        s  += __shfl_down_sync(0xffffffffu, s,  st);
        s2 += __shfl_down_sync(0xffffffffu, s2, st);
    }
    if (t==0){
        double N = (double)BATCH*8000.0;
        double mu = s/N;
        double var = s2/N - mu*mu;
        float a = gw[o] * (float)rsqrt(var + 1e-5);
        g_bn2a[o]=a; g_bn2bv[o]= gb[o] - (float)mu * a;
    }
}

__global__ void k_integrate(){
    int bf = blockIdx.x;
    int f = bf % F1;
    int t = threadIdx.x;
    float a = g_bn2a[f], bb = g_bn2bv[f];
    double s = 0.0;
    const float* h = g_h2 + (size_t)bf*8000;
    for (int idx=t; idx<8000; idx+=256){
        int k = idx/400;
        float v = h[idx]*a + bb;
        v = v>0.0f ? v : 0.0f;
        s += (double)v * (double)g_qw10[k];
    }
    __shared__ double sh[256];
    sh[t]=s; __syncthreads();
    for (int st=128; st>0; st>>=1){ if (t<st) sh[t]+=sh[t+st]; __syncthreads(); }
    if (t==0){
        double sc = (2.0*PI/20.0)*(2.0*PI/20.0);
        g_feat[bf] = (float)(sh[0]*sc);
    }
}

__global__ void k_lin(const float* __restrict__ lw, const float* __restrict__ lb,
                      float* __restrict__ out){
    int tid = blockIdx.x*blockDim.x + threadIdx.x;
    if (tid >= BATCH*NCLS) return;
    int c = tid % NCLS, b = tid / NCLS;
    float acc = lb[c];
    for (int f=0; f<F1; f++) acc += g_feat[b*F1+f]*lw[f*NCLS+c];
    out[tid] = acc;
}

// ================= host =================
extern "C" void kernel_launch(void* const* d_in, const int* in_sizes, int n_in,
                              void* d_out, int out_size){
    const float* x     = (const float*)d_in[0];
    const float* w_s2  = (const float*)d_in[1];
    const float* bn1g  = (const float*)d_in[3];
    const float* bn1b  = (const float*)d_in[4];
    const float* w_so3 = (const float*)d_in[5];
    const float* bn2g  = (const float*)d_in[7];
    const float* bn2b  = (const float*)d_in[8];
    const float* linw  = (const float*)d_in[9];
    const float* linb  = (const float*)d_in[10];
    float* out = (float*)d_out;

    k_setup<<<(TSETUP+255)/256,256>>>();                       // 1
    k_pre<<<PREGRID,256>>>(w_s2);                              // 2
    k_front<<<BATCH,256>>>(x);                                 // 3
    k_syn1<<<BATCH*F0,256>>>();                                // 4  <- profiled
    k_bnw<<<100 + (F0*F1*MR2+255)/256,256>>>(bn1g,bn1b,w_so3); // 5
    k_g2f<<<BATCH*F0,256>>>();                                 // 6
    k_z2<<<(BATCH*25*NH2+255)/256,256>>>();                    // 7
    k_syn2<<<BATCH*F1,256>>>();                                // 8
    k_bn2fin<<<F1,32>>>(bn2g, bn2b);                           // 9
    k_integrate<<<BATCH*F1,256>>>();                           // 10
    k_lin<<<(BATCH*NCLS+255)/256,256>>>(linw, linb, out);      // 11
}